// round 7
// baseline (speedup 1.0000x reference)
#include <cuda_runtime.h>
#include <cuda_bf16.h>
#include <cstdint>

#define HIDDEN   512
#define LATENT   128
#define NTOT     768          // 128 (mu) + 512 (u) + 128 (d)
#define MROWS    128          // rows per CTA
#define THREADS  288          // 8 consumer warps + 1 producer warp
#define NCONS    256
#define KTILEB   128          // k bytes per stage (int8)
#define NSTAGES  24           // 6 chunks x 4 k-tiles
#define NRING    4
#define XSTRB    528          // 512 + 16 pad; /16 = 33 odd -> conflict-free ldmatrix
#define WSTRB    144          // 128 + 16 pad; /16 = 9 odd  -> conflict-free ldmatrix
#define WS_BYTES (128 * WSTRB)         // 18432 per stage
#define RSTRIDE  132
#define NSTATS   16
#define XCLIP    5.0f
#define QSX      (127.0f / XCLIP)      // x quant scale
#define SXF      (XCLIP / 127.0f)      // x dequant factor

// W fused+reordered, int8 [n=768][k=512]; n = [mu 0-127 | u 128-639 | d 640-767]
__device__ int8_t g_Wq[(size_t)NTOT * HIDDEN];
__device__ float  g_swn[NTOT];         // per-column dequant scale
__device__ double g_sum;

__global__ void zero_kernel() { g_sum = 0.0; }

// one block per output column n: compute colmax, quantize to int8
__global__ void quantW_kernel(const float* __restrict__ W_mu,
                              const float* __restrict__ W_u,
                              const float* __restrict__ W_d) {
    const int n   = blockIdx.x;
    const int tid = threadIdx.x;       // 128 threads
    const float* col; int ld;
    if (n < 128)      { col = W_mu + n;         ld = 128; }
    else if (n < 640) { col = W_u + (n - 128);  ld = 512; }
    else              { col = W_d + (n - 640);  ld = 128; }

    float v[4]; float m = 0.f;
    #pragma unroll
    for (int j = 0; j < 4; j++) {
        v[j] = col[(size_t)(tid * 4 + j) * ld];
        m = fmaxf(m, fabsf(v[j]));
    }
    // block max reduce
    #pragma unroll
    for (int off = 16; off; off >>= 1)
        m = fmaxf(m, __shfl_xor_sync(~0u, m, off));
    __shared__ float red[4];
    if ((tid & 31) == 0) red[tid >> 5] = m;
    __syncthreads();
    float mx = fmaxf(fmaxf(red[0], red[1]), fmaxf(red[2], red[3]));
    float safe = (mx > 0.f) ? mx : 1.f;
    float inv = 127.0f / safe;

    char4 q;
    q.x = (char)__float2int_rn(v[0] * inv);
    q.y = (char)__float2int_rn(v[1] * inv);
    q.z = (char)__float2int_rn(v[2] * inv);
    q.w = (char)__float2int_rn(v[3] * inv);
    *(char4*)(g_Wq + (size_t)n * HIDDEN + tid * 4) = q;
    if (tid == 0) g_swn[n] = safe / 127.0f;
}

__device__ __forceinline__ unsigned smem_u32(const void* p) {
    return (unsigned)__cvta_generic_to_shared(p);
}
__device__ __forceinline__ void ldsm4(unsigned& r0, unsigned& r1, unsigned& r2, unsigned& r3, unsigned a) {
    asm volatile("ldmatrix.sync.aligned.m8n8.x4.shared.b16 {%0,%1,%2,%3}, [%4];"
                 : "=r"(r0), "=r"(r1), "=r"(r2), "=r"(r3) : "r"(a));
}
__device__ __forceinline__ void imma16832(int* c,
                                          unsigned a0, unsigned a1, unsigned a2, unsigned a3,
                                          unsigned b0, unsigned b1) {
    asm volatile("mma.sync.aligned.m16n8k32.row.col.s32.s8.s8.s32 "
                 "{%0,%1,%2,%3},{%4,%5,%6,%7},{%8,%9},{%0,%1,%2,%3};"
                 : "+r"(c[0]), "+r"(c[1]), "+r"(c[2]), "+r"(c[3])
                 : "r"(a0), "r"(a1), "r"(a2), "r"(a3), "r"(b0), "r"(b1));
}
__device__ __forceinline__ void cpasync16(unsigned dst, const void* src) {
    asm volatile("cp.async.cg.shared.global [%0], [%1], 16;" :: "r"(dst), "l"(src) : "memory");
}
#define CP_COMMIT() asm volatile("cp.async.commit_group;" ::: "memory")
#define CP_WAIT(n)  asm volatile("cp.async.wait_group %0;" :: "n"(n) : "memory")

#define MBARRIER_INIT(addr, cnt) \
    asm volatile("mbarrier.init.shared.b64 [%0], %1;" :: "r"((unsigned)(addr)), "r"((unsigned)(cnt)) : "memory")
#define MBARRIER_ARRIVE(addr) \
    asm volatile("mbarrier.arrive.shared.b64 _, [%0];" :: "r"((unsigned)(addr)) : "memory")
#define MBARRIER_WAIT_PARITY(mbar, par) do { \
    unsigned _m = (mbar); unsigned _p = (par); unsigned _done; \
    asm volatile( \
        "{\n\t.reg .pred p;\n\t" \
        "mbarrier.try_wait.parity.acquire.cta.shared::cta.b64 p, [%1], %2;\n\t" \
        "selp.b32 %0, 1, 0, p;\n\t}" \
        : "=r"(_done) : "r"(_m), "r"(_p) : "memory"); \
    if (!_done) { \
        asm volatile( \
            "{\n\t.reg .pred P1;\n\t" \
            "WL_%=:\n\t" \
            "mbarrier.try_wait.parity.acquire.cta.shared::cta.b64 P1, [%0], %1, 0x989680;\n\t" \
            "@P1 bra.uni WD_%=;\n\t" \
            "bra.uni WL_%=;\n\t" \
            "WD_%=:\n\t}" \
            :: "r"(_m), "r"(_p) : "memory"); \
    } \
} while(0)

extern __shared__ char smem_raw[];

__global__ void __launch_bounds__(THREADS, 1)
lrg_main(const float* __restrict__ x,
         const float* __restrict__ b_mu,
         const float* __restrict__ b_u,
         const float* __restrict__ b_d)
{
    // ---- shared memory layout ----
    char* xs = smem_raw;                                        // [128][XSTRB] int8   67,584 B
    char* ws = xs + MROWS * XSTRB;                              // 4 x [128][WSTRB]    73,728 B
    __nv_bfloat16* rs = (__nv_bfloat16*)(ws + NRING * WS_BYTES);// [128][RSTRIDE] bf16 33,792 B
    float* stats = (float*)(rs + 128 * RSTRIDE);                // [128][NSTATS]        8,192 B
    float* sws   = stats + 128 * NSTATS;                        // 768 col scales       3,072 B
    char*  barmem = (char*)(sws + NTOT);                        // 8 mbarriers x 8B

    const int tid  = threadIdx.x;
    const int wid  = tid >> 5;
    const int lane = tid & 31;

    const unsigned xs_base  = smem_u32(xs);
    const unsigned ws_base  = smem_u32(ws);
    const unsigned bar_base = smem_u32(barmem);

    if (tid == 0) {
        #pragma unroll
        for (int i = 0; i < NRING; i++) {
            MBARRIER_INIT(bar_base + i * 8, 1);            // FULL[i]
            MBARRIER_INIT(bar_base + 32 + i * 8, 8);       // EMPTY[i]
        }
    }
    __syncthreads();

    // chunk order: mu, d, u0..u3 (d before u so rsqrt(d) ready)
    const int nb_tab[6] = {0, 640, 128, 256, 384, 512};

    if (wid == 8) {
        // ================== producer warp: stream W stages via cp.async ==================
        int ph_e[NRING] = {1, 1, 1, 1};
        #pragma unroll 1
        for (int s = 0; s < NSTAGES; s++) {
            const int slot = s & 3;
            MBARRIER_WAIT_PARITY(bar_base + 32 + slot * 8, ph_e[slot]);
            ph_e[slot] ^= 1;
            const int nb = nb_tab[s >> 2];
            const int kt = s & 3;
            const int8_t* srcb = g_Wq + (size_t)nb * HIDDEN + kt * KTILEB;
            const unsigned dbase = ws_base + (unsigned)(slot * WS_BYTES);
            #pragma unroll 8
            for (int c = lane; c < 1024; c += 32) {        // 128n x 8 x 16B
                int n   = c >> 3;
                int k16 = c & 7;
                cpasync16(dbase + (unsigned)(n * WSTRB + k16 * 16),
                          srcb + (size_t)n * HIDDEN + k16 * 16);
            }
            CP_COMMIT();
            if (s > 0) {
                CP_WAIT(1);
                if (lane == 0) MBARRIER_ARRIVE(bar_base + ((s - 1) & 3) * 8);
            }
        }
        CP_WAIT(0);
        if (lane == 0) MBARRIER_ARRIVE(bar_base + ((NSTAGES - 1) & 3) * 8);
    } else {
        // ================== consumer warps 0-7 ==================
        const int q  = lane & 3;
        const int g  = lane >> 2;
        const int r0 = wid * 16 + g;
        const int r1 = r0 + 8;
        const int rowbase = blockIdx.x * MROWS;

        for (int i = tid; i < 128 * NSTATS; i += NCONS) stats[i] = 0.f;
        for (int i = tid; i < NTOT; i += NCONS) sws[i] = g_swn[i] * SXF;  // fold x scale

        // stage + quantize x block: fp32 global -> int8 smem (fixed scale)
        {
            const float4* xg = (const float4*)(x + (size_t)rowbase * HIDDEN);
            #pragma unroll 4
            for (int i = tid; i < MROWS * (HIDDEN / 4); i += NCONS) {
                int row = i >> 7;
                int c4  = i & 127;
                float4 v = xg[i];
                int q0 = __float2int_rn(fminf(fmaxf(v.x * QSX, -127.f), 127.f));
                int q1 = __float2int_rn(fminf(fmaxf(v.y * QSX, -127.f), 127.f));
                int q2 = __float2int_rn(fminf(fmaxf(v.z * QSX, -127.f), 127.f));
                int q3 = __float2int_rn(fminf(fmaxf(v.w * QSX, -127.f), 127.f));
                unsigned packed = (q0 & 0xFF) | ((q1 & 0xFF) << 8) |
                                  ((q2 & 0xFF) << 16) | ((unsigned)(q3 & 0xFF) << 24);
                *(unsigned*)(xs + row * XSTRB + c4 * 4) = packed;
            }
        }
        asm volatile("bar.sync 1, %0;" :: "n"(NCONS) : "memory");

        // ldmatrix per-lane addressing (16B-tile granularity on int8)
        const int t8 = lane >> 3;
        const int ri = lane & 7;
        // A tiles: t0=(m0-7,kB0-15) t1=(m8-15,kB0-15) t2=(m0-7,kB16-31) t3=(m8-15,kB16-31)
        const unsigned a_addr0 = xs_base +
            (unsigned)((wid * 16 + ((t8 & 1) << 3) + ri) * XSTRB + (((t8 >> 1) & 1) << 4));
        // B tiles: t0=(n0-7,kB0-15) t1=(n0-7,kB16-31) t2=(n8-15,kB0-15) t3=(n8-15,kB16-31)
        const unsigned b_addr0 = ws_base +
            (unsigned)(((((t8 >> 1) & 1) << 3) + ri) * WSTRB + ((t8 & 1) << 4));

        int acc[16][4];
        int ph_f[NRING] = {0, 0, 0, 0};

        #pragma unroll 1
        for (int s = 0; s < NSTAGES; s++) {
            const int slot = s & 3;
            const int ch = s >> 2;
            const int kt = s & 3;

            MBARRIER_WAIT_PARITY(bar_base + slot * 8, ph_f[slot]);
            ph_f[slot] ^= 1;

            if (kt == 0) {
                #pragma unroll
                for (int i = 0; i < 16; i++) { acc[i][0] = acc[i][1] = acc[i][2] = acc[i][3] = 0; }
            }

            const unsigned b_st = b_addr0 + (unsigned)(slot * WS_BYTES);
            const int k0 = kt * KTILEB;
            #pragma unroll
            for (int ks = 0; ks < 4; ks++) {               // k32 per step
                unsigned a0, a1, a2, a3;
                ldsm4(a0, a1, a2, a3, a_addr0 + (unsigned)(k0 + ks * 32));
                #pragma unroll
                for (int p = 0; p < 8; p++) {              // 16 n per group
                    unsigned b0, b1, b2, b3;
                    ldsm4(b0, b1, b2, b3, b_st + (unsigned)(p * 16 * WSTRB + ks * 32));
                    imma16832(acc[2 * p],     a0, a1, a2, a3, b0, b1);
                    imma16832(acc[2 * p + 1], a0, a1, a2, a3, b2, b3);
                }
            }
            if (lane == 0) MBARRIER_ARRIVE(bar_base + 32 + slot * 8);

            if (kt != 3) continue;

            // ================= fused epilogue for chunk ch =================
            const int nb = nb_tab[ch];
            if (ch == 0) {
                float s0 = 0.f, s1 = 0.f;
                #pragma unroll
                for (int ni = 0; ni < 16; ni++) {
                    int ncol = ni * 8 + q * 2;
                    float sc0 = sws[nb + ncol], sc1 = sws[nb + ncol + 1];
                    float bv0 = __ldg(b_mu + ncol), bv1 = __ldg(b_mu + ncol + 1);
                    float v0 = (float)acc[ni][0] * sc0 + bv0, v1 = (float)acc[ni][1] * sc1 + bv1;
                    float v2 = (float)acc[ni][2] * sc0 + bv0, v3 = (float)acc[ni][3] * sc1 + bv1;
                    s0 += v0 * v0 + v1 * v1;
                    s1 += v2 * v2 + v3 * v3;
                }
                s0 += __shfl_xor_sync(~0u, s0, 1); s0 += __shfl_xor_sync(~0u, s0, 2);
                s1 += __shfl_xor_sync(~0u, s1, 1); s1 += __shfl_xor_sync(~0u, s1, 2);
                if (q == 0) { stats[r0 * NSTATS + 0] += s0; stats[r1 * NSTATS + 0] += s1; }
            } else if (ch == 1) {
                float sd0 = 0.f, sd1 = 0.f, sz0 = 0.f, sz1 = 0.f;
                #pragma unroll
                for (int ni = 0; ni < 16; ni++) {
                    int ncol = ni * 8 + q * 2;
                    float sc0 = sws[nb + ncol], sc1 = sws[nb + ncol + 1];
                    float bv0 = __ldg(b_d + ncol), bv1 = __ldg(b_d + ncol + 1);
                    float z0 = (float)acc[ni][0] * sc0 + bv0, z1 = (float)acc[ni][1] * sc1 + bv1;
                    float z2 = (float)acc[ni][2] * sc0 + bv0, z3 = (float)acc[ni][3] * sc1 + bv1;
                    sd0 += expf(z0) + expf(z1);
                    sd1 += expf(z2) + expf(z3);
                    sz0 += z0 + z1;
                    sz1 += z2 + z3;
                    rs[r0 * RSTRIDE + ncol]     = __float2bfloat16(expf(-0.5f * z0));
                    rs[r0 * RSTRIDE + ncol + 1] = __float2bfloat16(expf(-0.5f * z1));
                    rs[r1 * RSTRIDE + ncol]     = __float2bfloat16(expf(-0.5f * z2));
                    rs[r1 * RSTRIDE + ncol + 1] = __float2bfloat16(expf(-0.5f * z3));
                }
                sd0 += __shfl_xor_sync(~0u, sd0, 1); sd0 += __shfl_xor_sync(~0u, sd0, 2);
                sd1 += __shfl_xor_sync(~0u, sd1, 1); sd1 += __shfl_xor_sync(~0u, sd1, 2);
                sz0 += __shfl_xor_sync(~0u, sz0, 1); sz0 += __shfl_xor_sync(~0u, sz0, 2);
                sz1 += __shfl_xor_sync(~0u, sz1, 1); sz1 += __shfl_xor_sync(~0u, sz1, 2);
                if (q == 0) {
                    stats[r0 * NSTATS + 1] += sd0; stats[r1 * NSTATS + 1] += sd1;
                    stats[r0 * NSTATS + 2] += sz0; stats[r1 * NSTATS + 2] += sz1;
                }
            } else {
                const int ubase = nb - 128;
                float su0 = 0.f, su1 = 0.f;
                float mac0[10], mac1[10];
                #pragma unroll
                for (int i = 0; i < 10; i++) { mac0[i] = 0.f; mac1[i] = 0.f; }
                #pragma unroll
                for (int ni = 0; ni < 16; ni++) {
                    int ncol = ni * 8 + q * 2;
                    int gcol = ubase + ncol;
                    float sc0 = sws[nb + ncol], sc1 = sws[nb + ncol + 1];
                    float bv0 = __ldg(b_u + gcol), bv1 = __ldg(b_u + gcol + 1);
                    float u0 = (float)acc[ni][0] * sc0 + bv0, u1 = (float)acc[ni][1] * sc1 + bv1;
                    float u2 = (float)acc[ni][2] * sc0 + bv0, u3 = (float)acc[ni][3] * sc1 + bv1;
                    su0 += u0 * u0 + u1 * u1;
                    su1 += u2 * u2 + u3 * u3;
                    int l = gcol >> 2;
                    float rv0 = __bfloat162float(rs[r0 * RSTRIDE + l]);
                    float rv1 = __bfloat162float(rs[r1 * RSTRIDE + l]);
                    float m0 = u0 * rv0, m1 = u1 * rv0;
                    float m2 = u2 * rv1, m3 = u3 * rv1;
                    float p0 = __shfl_xor_sync(~0u, m0, 1);
                    float p1 = __shfl_xor_sync(~0u, m1, 1);
                    float p2 = __shfl_xor_sync(~0u, m2, 1);
                    float p3 = __shfl_xor_sync(~0u, m3, 1);
                    float v0[4] = { m0, m1, p0, p1 };
                    float v1[4] = { m2, m3, p2, p3 };
                    #pragma unroll
                    for (int i2 = 0; i2 < 4; i2++)
                        #pragma unroll
                        for (int j2 = 0; j2 <= i2; j2++) {
                            mac0[i2 * (i2 + 1) / 2 + j2] += v0[i2] * v0[j2];
                            mac1[i2 * (i2 + 1) / 2 + j2] += v1[i2] * v1[j2];
                        }
                }
                su0 += __shfl_xor_sync(~0u, su0, 1); su0 += __shfl_xor_sync(~0u, su0, 2);
                su1 += __shfl_xor_sync(~0u, su1, 1); su1 += __shfl_xor_sync(~0u, su1, 2);
                #pragma unroll
                for (int i = 0; i < 10; i++) {
                    mac0[i] += __shfl_xor_sync(~0u, mac0[i], 2);
                    mac1[i] += __shfl_xor_sync(~0u, mac1[i], 2);
                }
                if (q == 0) {
                    stats[r0 * NSTATS + 3] += su0;
                    stats[r1 * NSTATS + 3] += su1;
                    #pragma unroll
                    for (int i = 0; i < 10; i++) {
                        stats[r0 * NSTATS + 4 + i] += mac0[i];
                        stats[r1 * NSTATS + 4 + i] += mac1[i];
                    }
                }
            }
        }
    }

    __syncthreads();        // stats visible (producer joins too)

    // ---- per-row finish: logdet(I + MtM) via 4x4 Cholesky, then KL ----
    double klsum = 0.0;
    if (tid < MROWS) {
        const float* st = stats + tid * NSTATS;
        float mu_sq = st[0], sum_d = st[1], logz = st[2], su = st[3];
        float a00 = 1.f + st[4];
        float a10 = st[5],  a11 = 1.f + st[6];
        float a20 = st[7],  a21 = st[8],  a22 = 1.f + st[9];
        float a30 = st[10], a31 = st[11], a32 = st[12], a33 = 1.f + st[13];
        float L00 = sqrtf(a00); float i0 = 1.f / L00;
        float L10 = a10 * i0, L20 = a20 * i0, L30 = a30 * i0;
        float L11 = sqrtf(a11 - L10 * L10); float i1 = 1.f / L11;
        float L21 = (a21 - L20 * L10) * i1;
        float L31 = (a31 - L30 * L10) * i1;
        float L22 = sqrtf(a22 - L20 * L20 - L21 * L21); float i2 = 1.f / L22;
        float L32 = (a32 - L30 * L20 - L31 * L21) * i2;
        float L33 = sqrtf(a33 - L30 * L30 - L31 * L31 - L32 * L32);
        float logdetlr = 2.f * (logf(L00) + logf(L11) + logf(L22) + logf(L33));
        float kl = 0.5f * (sum_d + su + mu_sq - (float)LATENT - logz - logdetlr);
        klsum = (double)kl;
    }
    #pragma unroll
    for (int off = 16; off; off >>= 1) klsum += __shfl_down_sync(~0u, klsum, off);
    __shared__ double wsum[9];
    if (lane == 0) wsum[wid] = klsum;
    __syncthreads();
    if (tid == 0) {
        double ssum = 0.0;
        #pragma unroll
        for (int i = 0; i < 9; i++) ssum += wsum[i];
        atomicAdd(&g_sum, ssum);
    }
}

__global__ void finalize_kernel(float* out, int N) {
    out[0] = (float)(g_sum / (double)N);
}

extern "C" void kernel_launch(void* const* d_in, const int* in_sizes, int n_in,
                              void* d_out, int out_size) {
    const float* x    = (const float*)d_in[0];
    const float* W_mu = (const float*)d_in[1];
    const float* b_mu = (const float*)d_in[2];
    const float* W_u  = (const float*)d_in[3];
    const float* b_u  = (const float*)d_in[4];
    const float* W_d  = (const float*)d_in[5];
    const float* b_d  = (const float*)d_in[6];
    const int N = in_sizes[0] / HIDDEN;

    const size_t smem_bytes =
        (size_t)MROWS * XSTRB + (size_t)NRING * WS_BYTES +
        (size_t)128 * RSTRIDE * sizeof(__nv_bfloat16) +
        (size_t)(128 * NSTATS + NTOT) * sizeof(float) + 64;

    cudaFuncSetAttribute(lrg_main, cudaFuncAttributeMaxDynamicSharedMemorySize,
                         (int)smem_bytes);

    zero_kernel<<<1, 1>>>();
    quantW_kernel<<<NTOT, 128>>>(W_mu, W_u, W_d);
    lrg_main<<<N / MROWS, THREADS, smem_bytes>>>(x, b_mu, b_u, b_d);
    finalize_kernel<<<1, 1>>>((float*)d_out, N);
}

// round 8
// speedup vs baseline: 1.5503x; 1.5503x over previous
#include <cuda_runtime.h>
#include <cuda_bf16.h>
#include <cstdint>

#define HIDDEN   512
#define LATENT   128
#define NTOT     768          // 128 (mu) + 512 (u) + 128 (d)
#define MROWS    64           // rows per CTA (occupancy 2)
#define THREADS  256
#define KTILE    32
#define XSTRIDE  520          // 512 + 8 bf16 (1040B row, /16 odd -> conflict-free ldmatrix)
#define WSTRIDE  40           // 32 + 8 bf16  (80B row, /16 odd  -> conflict-free)
#define WS_ELEMS (128 * WSTRIDE)       // per stage (128 n-cols x 32 k)
#define RSTRIDE  132
#define NSTATS   16
#define NSTAGES  96           // 6 chunks x 16 k-tiles

// W fused+transposed bf16, layout [n=768][k=512]: n = [mu 0-127 | u 128-639 | d 640-767]
__device__ __nv_bfloat16 g_Wt[(size_t)NTOT * HIDDEN];
__device__ double g_sum;

__global__ void zero_kernel() { g_sum = 0.0; }

__global__ void convertW_kernel(const float* __restrict__ W_mu,
                                const float* __restrict__ W_u,
                                const float* __restrict__ W_d) {
    int i = blockIdx.x * blockDim.x + threadIdx.x;     // i = k*768 + n (coalesced reads)
    if (i >= NTOT * HIDDEN) return;
    int k = i / NTOT;
    int n = i - k * NTOT;
    float v;
    if (n < 128)       v = W_mu[k * 128 + n];
    else if (n < 640)  v = W_u [k * 512 + (n - 128)];
    else               v = W_d [k * 128 + (n - 640)];
    g_Wt[(size_t)n * HIDDEN + k] = __float2bfloat16(v);
}

__device__ __forceinline__ unsigned smem_u32(const void* p) {
    return (unsigned)__cvta_generic_to_shared(p);
}
__device__ __forceinline__ void ldsm4(unsigned& r0, unsigned& r1, unsigned& r2, unsigned& r3, unsigned a) {
    asm volatile("ldmatrix.sync.aligned.m8n8.x4.shared.b16 {%0,%1,%2,%3}, [%4];"
                 : "=r"(r0), "=r"(r1), "=r"(r2), "=r"(r3) : "r"(a));
}
__device__ __forceinline__ void mma16816(float* c,
                                         unsigned a0, unsigned a1, unsigned a2, unsigned a3,
                                         unsigned b0, unsigned b1) {
    asm volatile("mma.sync.aligned.m16n8k16.row.col.f32.bf16.bf16.f32 "
                 "{%0,%1,%2,%3},{%4,%5,%6,%7},{%8,%9},{%0,%1,%2,%3};"
                 : "+f"(c[0]), "+f"(c[1]), "+f"(c[2]), "+f"(c[3])
                 : "r"(a0), "r"(a1), "r"(a2), "r"(a3), "r"(b0), "r"(b1));
}
__device__ __forceinline__ void cpasync16(unsigned dst, const void* src) {
    asm volatile("cp.async.cg.shared.global [%0], [%1], 16;" :: "r"(dst), "l"(src) : "memory");
}
#define CP_COMMIT() asm volatile("cp.async.commit_group;" ::: "memory")
#define CP_WAIT(n)  asm volatile("cp.async.wait_group %0;" :: "n"(n) : "memory")

extern __shared__ char smem_raw[];

__global__ void __launch_bounds__(THREADS, 2)
lrg_main(const float* __restrict__ x,
         const float* __restrict__ b_mu,
         const float* __restrict__ b_u,
         const float* __restrict__ b_d)
{
    // ---- shared memory layout (105.5 KB dynamic -> 2 CTAs/SM) ----
    __nv_bfloat16* xs = (__nv_bfloat16*)smem_raw;              // [64][XSTRIDE] bf16   66,560 B
    __nv_bfloat16* ws = xs + MROWS * XSTRIDE;                  // 2 x [128][WSTRIDE]   20,480 B
    __nv_bfloat16* rs = ws + 2 * WS_ELEMS;                     // [64][RSTRIDE] bf16   16,896 B
    float* stats = (float*)(rs + MROWS * RSTRIDE);             // [64][NSTATS] fp32     4,096 B

    const int tid  = threadIdx.x;
    const int wid  = tid >> 5;
    const int lane = tid & 31;
    const int mw   = wid & 3;          // M group (16 rows)
    const int nh   = wid >> 2;         // N half (64 cols)
    const int q    = lane & 3;
    const int g    = lane >> 2;
    const int r0   = mw * 16 + g;
    const int r1   = r0 + 8;
    const int rowbase = blockIdx.x * MROWS;

    for (int i = tid; i < MROWS * NSTATS; i += THREADS) stats[i] = 0.f;

    // ---- stage x block: fp32 global -> bf16 smem ----
    {
        const float4* xg = (const float4*)(x + (size_t)rowbase * HIDDEN);
        #pragma unroll 4
        for (int i = tid; i < MROWS * (HIDDEN / 4); i += THREADS) {
            int row = i >> 7;
            int c4  = i & 127;
            float4 v = xg[i];
            __nv_bfloat162* dst = (__nv_bfloat162*)(xs + row * XSTRIDE + c4 * 4);
            dst[0] = __floats2bfloat162_rn(v.x, v.y);
            dst[1] = __floats2bfloat162_rn(v.z, v.w);
        }
    }

    // ---- ldmatrix per-lane addressing ----
    const int t8 = lane >> 3;
    const int ri = lane & 7;
    const unsigned xs_base = smem_u32(xs);
    const unsigned ws_base = smem_u32(ws);
    // A tiles: t0=(m0-7,k0-7) t1=(m8-15,k0-7) t2=(m0-7,k8-15) t3=(m8-15,k8-15)
    const unsigned a_addr0 = xs_base +
        (unsigned)(((mw * 16 + ((t8 & 1) << 3) + ri) * XSTRIDE + (((t8 >> 1) & 1) << 3)) * 2);
    // B tiles: t0=(n0-7,k0-7) t1=(n0-7,k8-15) t2=(n8-15,k0-7) t3=(n8-15,k8-15); n offset nh*64
    const unsigned b_addr0 = ws_base +
        (unsigned)(((nh * 64 + (((t8 >> 1) & 1) << 3) + ri) * WSTRIDE + ((t8 & 1) << 3)) * 2);

    // chunk order: mu, d, u0..u3 (d before u so rsqrt(d) ready)
    const int nb_tab[6] = {0, 640, 128, 256, 384, 512};

    // cp.async producer: W tile [128n][32k] -> ws buffer st
    auto issue_stage = [&](int s, int st) {
        const int nb = nb_tab[s >> 4];
        const int kt = s & 15;
        const __nv_bfloat16* srcb = g_Wt + (size_t)nb * HIDDEN + kt * KTILE;
        const unsigned dbase = ws_base + (unsigned)(st * WS_ELEMS * 2);
        #pragma unroll
        for (int c = tid; c < 512; c += THREADS) {      // 2 iters x 16B
            int n  = c >> 2;
            int kq = c & 3;
            cpasync16(dbase + (unsigned)(n * (WSTRIDE * 2) + kq * 16),
                      srcb + (size_t)n * HIDDEN + kq * 8);
        }
        CP_COMMIT();
    };

    __syncthreads();            // xs visible before first ldmatrix
    issue_stage(0, 0);

    float acc[8][4];

    #pragma unroll 1
    for (int s = 0; s < NSTAGES; s++) {
        const int st = s & 1;
        const int ch = s >> 4;
        const int kt = s & 15;

        if (s) __syncthreads();                 // prev stage consumption complete
        if (s + 1 < NSTAGES) issue_stage(s + 1, st ^ 1);
        if (s + 1 < NSTAGES) { CP_WAIT(1); } else { CP_WAIT(0); }
        __syncthreads();                        // stage s visible to all warps

        if (kt == 0) {
            #pragma unroll
            for (int i = 0; i < 8; i++) { acc[i][0] = acc[i][1] = acc[i][2] = acc[i][3] = 0.f; }
        }

        const unsigned b_st = b_addr0 + (unsigned)(st * WS_ELEMS * 2);
        const int k0 = kt * KTILE;
        #pragma unroll
        for (int ks = 0; ks < 2; ks++) {
            unsigned a0, a1, a2, a3;
            ldsm4(a0, a1, a2, a3, a_addr0 + (unsigned)((k0 + ks * 16) * 2));
            #pragma unroll
            for (int p = 0; p < 4; p++) {
                unsigned b0, b1, b2, b3;
                ldsm4(b0, b1, b2, b3,
                      b_st + (unsigned)(p * 16 * WSTRIDE * 2 + ks * 16 * 2));
                mma16816(acc[2 * p],     a0, a1, a2, a3, b0, b1);
                mma16816(acc[2 * p + 1], a0, a1, a2, a3, b2, b3);
            }
        }

        if (kt != 15) continue;

        // ================= fused epilogue for chunk ch =================
        // lane owns cols ncol = nh*64 + ni*8 + q*2 + {0,1}; rows r0 (c0,c1), r1 (c2,c3)
        if (ch == 0) {
            float s0 = 0.f, s1 = 0.f;
            #pragma unroll
            for (int ni = 0; ni < 8; ni++) {
                int ncol = nh * 64 + ni * 8 + q * 2;
                float bv0 = __ldg(b_mu + ncol), bv1 = __ldg(b_mu + ncol + 1);
                float v0 = acc[ni][0] + bv0, v1 = acc[ni][1] + bv1;
                float v2 = acc[ni][2] + bv0, v3 = acc[ni][3] + bv1;
                s0 += v0 * v0 + v1 * v1;
                s1 += v2 * v2 + v3 * v3;
            }
            s0 += __shfl_xor_sync(~0u, s0, 1); s0 += __shfl_xor_sync(~0u, s0, 2);
            s1 += __shfl_xor_sync(~0u, s1, 1); s1 += __shfl_xor_sync(~0u, s1, 2);
            if (q == 0) {
                atomicAdd(&stats[r0 * NSTATS + 0], s0);
                atomicAdd(&stats[r1 * NSTATS + 0], s1);
            }
        } else if (ch == 1) {
            float sd0 = 0.f, sd1 = 0.f, sz0 = 0.f, sz1 = 0.f;
            #pragma unroll
            for (int ni = 0; ni < 8; ni++) {
                int ncol = nh * 64 + ni * 8 + q * 2;
                float bv0 = __ldg(b_d + ncol), bv1 = __ldg(b_d + ncol + 1);
                float z0 = acc[ni][0] + bv0, z1 = acc[ni][1] + bv1;
                float z2 = acc[ni][2] + bv0, z3 = acc[ni][3] + bv1;
                sd0 += expf(z0) + expf(z1);
                sd1 += expf(z2) + expf(z3);
                sz0 += z0 + z1;
                sz1 += z2 + z3;
                rs[r0 * RSTRIDE + ncol]     = __float2bfloat16(expf(-0.5f * z0));
                rs[r0 * RSTRIDE + ncol + 1] = __float2bfloat16(expf(-0.5f * z1));
                rs[r1 * RSTRIDE + ncol]     = __float2bfloat16(expf(-0.5f * z2));
                rs[r1 * RSTRIDE + ncol + 1] = __float2bfloat16(expf(-0.5f * z3));
            }
            sd0 += __shfl_xor_sync(~0u, sd0, 1); sd0 += __shfl_xor_sync(~0u, sd0, 2);
            sd1 += __shfl_xor_sync(~0u, sd1, 1); sd1 += __shfl_xor_sync(~0u, sd1, 2);
            sz0 += __shfl_xor_sync(~0u, sz0, 1); sz0 += __shfl_xor_sync(~0u, sz0, 2);
            sz1 += __shfl_xor_sync(~0u, sz1, 1); sz1 += __shfl_xor_sync(~0u, sz1, 2);
            if (q == 0) {
                atomicAdd(&stats[r0 * NSTATS + 1], sd0);
                atomicAdd(&stats[r1 * NSTATS + 1], sd1);
                atomicAdd(&stats[r0 * NSTATS + 2], sz0);
                atomicAdd(&stats[r1 * NSTATS + 2], sz1);
            }
        } else {
            const int ubase = nb_tab[ch] - 128;
            float su0 = 0.f, su1 = 0.f;
            float mac0[10], mac1[10];
            #pragma unroll
            for (int i = 0; i < 10; i++) { mac0[i] = 0.f; mac1[i] = 0.f; }
            #pragma unroll
            for (int ni = 0; ni < 8; ni++) {
                int ncol = nh * 64 + ni * 8 + q * 2;
                int gcol = ubase + ncol;                  // global u column = l*4 + r
                float bv0 = __ldg(b_u + gcol), bv1 = __ldg(b_u + gcol + 1);
                float u0 = acc[ni][0] + bv0, u1 = acc[ni][1] + bv1;
                float u2 = acc[ni][2] + bv0, u3 = acc[ni][3] + bv1;
                su0 += u0 * u0 + u1 * u1;
                su1 += u2 * u2 + u3 * u3;
                int l = gcol >> 2;
                float rv0 = __bfloat162float(rs[r0 * RSTRIDE + l]);
                float rv1 = __bfloat162float(rs[r1 * RSTRIDE + l]);
                float m0 = u0 * rv0, m1 = u1 * rv0;       // even q: ranks (0,1); odd q: (2,3)
                float m2 = u2 * rv1, m3 = u3 * rv1;
                float p0 = __shfl_xor_sync(~0u, m0, 1);
                float p1 = __shfl_xor_sync(~0u, m1, 1);
                float p2 = __shfl_xor_sync(~0u, m2, 1);
                float p3 = __shfl_xor_sync(~0u, m3, 1);
                float v0[4] = { m0, m1, p0, p1 };
                float v1[4] = { m2, m3, p2, p3 };
                #pragma unroll
                for (int i2 = 0; i2 < 4; i2++)
                    #pragma unroll
                    for (int j2 = 0; j2 <= i2; j2++) {
                        mac0[i2 * (i2 + 1) / 2 + j2] += v0[i2] * v0[j2];
                        mac1[i2 * (i2 + 1) / 2 + j2] += v1[i2] * v1[j2];
                    }
            }
            su0 += __shfl_xor_sync(~0u, su0, 1); su0 += __shfl_xor_sync(~0u, su0, 2);
            su1 += __shfl_xor_sync(~0u, su1, 1); su1 += __shfl_xor_sync(~0u, su1, 2);
            #pragma unroll
            for (int i = 0; i < 10; i++) {    // combine even-latent (q0) + odd-latent (q2)
                mac0[i] += __shfl_xor_sync(~0u, mac0[i], 2);
                mac1[i] += __shfl_xor_sync(~0u, mac1[i], 2);
            }
            if (q == 0) {
                atomicAdd(&stats[r0 * NSTATS + 3], su0);
                atomicAdd(&stats[r1 * NSTATS + 3], su1);
                #pragma unroll
                for (int i = 0; i < 10; i++) {
                    atomicAdd(&stats[r0 * NSTATS + 4 + i], mac0[i]);
                    atomicAdd(&stats[r1 * NSTATS + 4 + i], mac1[i]);
                }
            }
        }
    }

    __syncthreads();

    // ---- per-row finish: logdet(I + MtM) via 4x4 Cholesky, then KL ----
    double klsum = 0.0;
    if (tid < MROWS) {
        const float* st = stats + tid * NSTATS;
        float mu_sq = st[0], sum_d = st[1], logz = st[2], su = st[3];
        float a00 = 1.f + st[4];
        float a10 = st[5],  a11 = 1.f + st[6];
        float a20 = st[7],  a21 = st[8],  a22 = 1.f + st[9];
        float a30 = st[10], a31 = st[11], a32 = st[12], a33 = 1.f + st[13];
        float L00 = sqrtf(a00); float i0 = 1.f / L00;
        float L10 = a10 * i0, L20 = a20 * i0, L30 = a30 * i0;
        float L11 = sqrtf(a11 - L10 * L10); float i1 = 1.f / L11;
        float L21 = (a21 - L20 * L10) * i1;
        float L31 = (a31 - L30 * L10) * i1;
        float L22 = sqrtf(a22 - L20 * L20 - L21 * L21); float i2 = 1.f / L22;
        float L32 = (a32 - L30 * L20 - L31 * L21) * i2;
        float L33 = sqrtf(a33 - L30 * L30 - L31 * L31 - L32 * L32);
        float logdetlr = 2.f * (logf(L00) + logf(L11) + logf(L22) + logf(L33));
        float kl = 0.5f * (sum_d + su + mu_sq - (float)LATENT - logz - logdetlr);
        klsum = (double)kl;
    }
    #pragma unroll
    for (int off = 16; off; off >>= 1) klsum += __shfl_down_sync(~0u, klsum, off);
    __shared__ double wsum[8];
    if (lane == 0) wsum[wid] = klsum;
    __syncthreads();
    if (tid == 0) {
        double ssum = 0.0;
        #pragma unroll
        for (int i = 0; i < 8; i++) ssum += wsum[i];
        atomicAdd(&g_sum, ssum);
    }
}

__global__ void finalize_kernel(float* out, int N) {
    out[0] = (float)(g_sum / (double)N);
}

extern "C" void kernel_launch(void* const* d_in, const int* in_sizes, int n_in,
                              void* d_out, int out_size) {
    const float* x    = (const float*)d_in[0];
    const float* W_mu = (const float*)d_in[1];
    const float* b_mu = (const float*)d_in[2];
    const float* W_u  = (const float*)d_in[3];
    const float* b_u  = (const float*)d_in[4];
    const float* W_d  = (const float*)d_in[5];
    const float* b_d  = (const float*)d_in[6];
    const int N = in_sizes[0] / HIDDEN;

    const size_t smem_bytes =
        (size_t)(MROWS * XSTRIDE + 2 * WS_ELEMS + MROWS * RSTRIDE) * sizeof(__nv_bfloat16) +
        (size_t)(MROWS * NSTATS) * sizeof(float);

    cudaFuncSetAttribute(lrg_main, cudaFuncAttributeMaxDynamicSharedMemorySize,
                         (int)smem_bytes);

    zero_kernel<<<1, 1>>>();
    convertW_kernel<<<(NTOT * HIDDEN + 255) / 256, 256>>>(W_mu, W_u, W_d);
    lrg_main<<<N / MROWS, THREADS, smem_bytes>>>(x, b_mu, b_u, b_d);
    finalize_kernel<<<1, 1>>>((float*)d_out, N);
}

// round 9
// speedup vs baseline: 1.8628x; 1.2016x over previous
#include <cuda_runtime.h>
#include <cuda_fp16.h>
#include <cstdint>

#define HIDDEN   512
#define LATENT   128
#define NTOT     768          // 128 (mu) + 512 (u) + 128 (d)
#define MROWS    128          // rows per CTA
#define THREADS  256
#define KTILE    64
#define XSTRIDE  520          // 512 + 8 fp16 -> conflict-free ldmatrix
#define WSTRIDE  72           // 64 + 8 fp16  -> conflict-free ldmatrix
#define WS_ELEMS (128 * WSTRIDE)       // per stage
#define RSTRIDE  132
#define NSTATS   16
#define NSTAGES  48           // 6 chunks x 8 k-tiles
#define NRING    3

// W fused+transposed fp16, layout [n=768][k=512]: n = [mu 0-127 | u 128-639 | d 640-767]
__device__ __half g_Wt[(size_t)NTOT * HIDDEN];
__device__ double g_sum;

__global__ void zero_kernel() { g_sum = 0.0; }

__global__ void convertW_kernel(const float* __restrict__ W_mu,
                                const float* __restrict__ W_u,
                                const float* __restrict__ W_d) {
    int i = blockIdx.x * blockDim.x + threadIdx.x;     // i = k*768 + n (coalesced reads)
    if (i >= NTOT * HIDDEN) return;
    int k = i / NTOT;
    int n = i - k * NTOT;
    float v;
    if (n < 128)       v = W_mu[k * 128 + n];
    else if (n < 640)  v = W_u [k * 512 + (n - 128)];
    else               v = W_d [k * 128 + (n - 640)];
    g_Wt[(size_t)n * HIDDEN + k] = __float2half_rn(v);
}

__device__ __forceinline__ unsigned smem_u32(const void* p) {
    return (unsigned)__cvta_generic_to_shared(p);
}
__device__ __forceinline__ void ldsm4(unsigned& r0, unsigned& r1, unsigned& r2, unsigned& r3, unsigned a) {
    asm volatile("ldmatrix.sync.aligned.m8n8.x4.shared.b16 {%0,%1,%2,%3}, [%4];"
                 : "=r"(r0), "=r"(r1), "=r"(r2), "=r"(r3) : "r"(a));
}
// fp16-accumulate HMMA: D,C are 2 b32 regs (4 halves): reg0 = row g cols(2q,2q+1), reg1 = row g+8
__device__ __forceinline__ void mma16816h(unsigned& c0, unsigned& c1,
                                          unsigned a0, unsigned a1, unsigned a2, unsigned a3,
                                          unsigned b0, unsigned b1) {
    asm volatile("mma.sync.aligned.m16n8k16.row.col.f16.f16.f16.f16 "
                 "{%0,%1},{%2,%3,%4,%5},{%6,%7},{%0,%1};"
                 : "+r"(c0), "+r"(c1)
                 : "r"(a0), "r"(a1), "r"(a2), "r"(a3), "r"(b0), "r"(b1));
}
__device__ __forceinline__ void cpasync16(unsigned dst, const void* src) {
    asm volatile("cp.async.cg.shared.global [%0], [%1], 16;" :: "r"(dst), "l"(src) : "memory");
}
#define CP_COMMIT() asm volatile("cp.async.commit_group;" ::: "memory")
#define CP_WAIT(n)  asm volatile("cp.async.wait_group %0;" :: "n"(n) : "memory")

extern __shared__ char smem_raw[];

__global__ void __launch_bounds__(THREADS, 1)
lrg_main(const float* __restrict__ x,
         const float* __restrict__ b_mu,
         const float* __restrict__ b_u,
         const float* __restrict__ b_d)
{
    // ---- shared memory layout (230,400 B dynamic) ----
    __half* xs = (__half*)smem_raw;                            // [128][XSTRIDE]      133,120 B
    __half* ws = xs + MROWS * XSTRIDE;                         // 3 x [128][WSTRIDE]   55,296 B
    __half* rs = ws + NRING * WS_ELEMS;                        // [128][RSTRIDE]       33,792 B
    float* stats = (float*)(rs + 128 * RSTRIDE);               // [128][NSTATS]         8,192 B

    const int tid  = threadIdx.x;
    const int wid  = tid >> 5;
    const int lane = tid & 31;
    const int q    = lane & 3;
    const int g    = lane >> 2;
    const int r0   = wid * 16 + g;
    const int r1   = r0 + 8;
    const int rowbase = blockIdx.x * MROWS;

    for (int i = tid; i < 128 * NSTATS; i += THREADS) stats[i] = 0.f;

    // ---- stage x block: fp32 global -> fp16 smem ----
    {
        const float4* xg = (const float4*)(x + (size_t)rowbase * HIDDEN);
        #pragma unroll 4
        for (int i = tid; i < MROWS * (HIDDEN / 4); i += THREADS) {
            int row = i >> 7;
            int c4  = i & 127;
            float4 v = xg[i];
            __half2* dst = (__half2*)(xs + row * XSTRIDE + c4 * 4);
            dst[0] = __floats2half2_rn(v.x, v.y);
            dst[1] = __floats2half2_rn(v.z, v.w);
        }
    }

    // ---- ldmatrix per-lane addressing ----
    const int t8 = lane >> 3;
    const int ri = lane & 7;
    const unsigned xs_base = smem_u32(xs);
    const unsigned ws_base = smem_u32(ws);
    const unsigned a_addr0 = xs_base +
        (unsigned)(((wid * 16 + ((t8 & 1) << 3) + ri) * XSTRIDE + (((t8 >> 1) & 1) << 3)) * 2);
    const unsigned b_addr0 = ws_base +
        (unsigned)((((((t8 >> 1) & 1) << 3) + ri) * WSTRIDE + ((t8 & 1) << 3)) * 2);

    // chunk order: mu, d, u0..u3 (d before u so rsqrt(d) ready)
    const int nb_tab[6] = {0, 640, 128, 256, 384, 512};

    // cp.async producer for one stage: W tile [128n][64k] -> ring slot
    auto issue_stage = [&](int s) {
        const int slot = s % NRING;
        const int nb = nb_tab[s >> 3];
        const int kt = s & 7;
        const __half* srcb = g_Wt + (size_t)nb * HIDDEN + kt * KTILE;
        const unsigned dbase = ws_base + (unsigned)(slot * WS_ELEMS * 2);
        #pragma unroll
        for (int c = tid; c < 1024; c += THREADS) {      // 4 iters x 16B
            int n  = c >> 3;
            int k8 = c & 7;
            cpasync16(dbase + (unsigned)(n * (WSTRIDE * 2) + k8 * 16),
                      srcb + (size_t)n * HIDDEN + k8 * 8);
        }
        CP_COMMIT();
    };

    // prologue: 2 stages in flight; barrier covers xs visibility too
    issue_stage(0);
    issue_stage(1);
    CP_WAIT(1);
    __syncthreads();

    unsigned acc[16][2];

    #pragma unroll 1
    for (int s = 0; s < NSTAGES; s++) {
        const int slot = s % NRING;
        const int ch = s >> 3;
        const int kt = s & 7;

        if (kt == 0) {
            #pragma unroll
            for (int i = 0; i < 16; i++) { acc[i][0] = 0u; acc[i][1] = 0u; }
        }

        const unsigned b_st = b_addr0 + (unsigned)(slot * WS_ELEMS * 2);
        const int k0 = kt * KTILE;
        #pragma unroll
        for (int ks = 0; ks < 4; ks++) {
            unsigned a0, a1, a2, a3;
            ldsm4(a0, a1, a2, a3, a_addr0 + (unsigned)((k0 + ks * 16) * 2));
            #pragma unroll
            for (int p = 0; p < 8; p++) {
                unsigned b0, b1, b2, b3;
                ldsm4(b0, b1, b2, b3,
                      b_st + (unsigned)(p * 16 * WSTRIDE * 2 + ks * 16 * 2));
                mma16816h(acc[2 * p][0],     acc[2 * p][1],     a0, a1, a2, a3, b0, b1);
                mma16816h(acc[2 * p + 1][0], acc[2 * p + 1][1], a0, a1, a2, a3, b2, b3);
            }
        }

        // issue next+1 stage into the slot stage s-1 used (all warps passed last barrier)
        if (s + 2 < NSTAGES) issue_stage(s + 2);

        if (kt == 7) {
            // ================= fused epilogue for chunk ch =================
            if (ch == 0) {
                float s0 = 0.f, s1 = 0.f;
                #pragma unroll
                for (int ni = 0; ni < 16; ni++) {
                    int ncol = ni * 8 + q * 2;
                    float bv0 = __ldg(b_mu + ncol), bv1 = __ldg(b_mu + ncol + 1);
                    float2 f0 = __half22float2(*(__half2*)&acc[ni][0]);
                    float2 f1 = __half22float2(*(__half2*)&acc[ni][1]);
                    float v0 = f0.x + bv0, v1 = f0.y + bv1;
                    float v2 = f1.x + bv0, v3 = f1.y + bv1;
                    s0 += v0 * v0 + v1 * v1;
                    s1 += v2 * v2 + v3 * v3;
                }
                s0 += __shfl_xor_sync(~0u, s0, 1); s0 += __shfl_xor_sync(~0u, s0, 2);
                s1 += __shfl_xor_sync(~0u, s1, 1); s1 += __shfl_xor_sync(~0u, s1, 2);
                if (q == 0) { stats[r0 * NSTATS + 0] += s0; stats[r1 * NSTATS + 0] += s1; }
            } else if (ch == 1) {
                float sd0 = 0.f, sd1 = 0.f, sz0 = 0.f, sz1 = 0.f;
                #pragma unroll
                for (int ni = 0; ni < 16; ni++) {
                    int ncol = ni * 8 + q * 2;
                    float bv0 = __ldg(b_d + ncol), bv1 = __ldg(b_d + ncol + 1);
                    float2 f0 = __half22float2(*(__half2*)&acc[ni][0]);
                    float2 f1 = __half22float2(*(__half2*)&acc[ni][1]);
                    float z0 = f0.x + bv0, z1 = f0.y + bv1;
                    float z2 = f1.x + bv0, z3 = f1.y + bv1;
                    sd0 += expf(z0) + expf(z1);
                    sd1 += expf(z2) + expf(z3);
                    sz0 += z0 + z1;
                    sz1 += z2 + z3;
                    rs[r0 * RSTRIDE + ncol]     = __float2half_rn(expf(-0.5f * z0));
                    rs[r0 * RSTRIDE + ncol + 1] = __float2half_rn(expf(-0.5f * z1));
                    rs[r1 * RSTRIDE + ncol]     = __float2half_rn(expf(-0.5f * z2));
                    rs[r1 * RSTRIDE + ncol + 1] = __float2half_rn(expf(-0.5f * z3));
                }
                sd0 += __shfl_xor_sync(~0u, sd0, 1); sd0 += __shfl_xor_sync(~0u, sd0, 2);
                sd1 += __shfl_xor_sync(~0u, sd1, 1); sd1 += __shfl_xor_sync(~0u, sd1, 2);
                sz0 += __shfl_xor_sync(~0u, sz0, 1); sz0 += __shfl_xor_sync(~0u, sz0, 2);
                sz1 += __shfl_xor_sync(~0u, sz1, 1); sz1 += __shfl_xor_sync(~0u, sz1, 2);
                if (q == 0) {
                    stats[r0 * NSTATS + 1] += sd0; stats[r1 * NSTATS + 1] += sd1;
                    stats[r0 * NSTATS + 2] += sz0; stats[r1 * NSTATS + 2] += sz1;
                }
            } else {
                const int ubase = nb_tab[ch] - 128;
                float su0 = 0.f, su1 = 0.f;
                float mac0[10], mac1[10];
                #pragma unroll
                for (int i = 0; i < 10; i++) { mac0[i] = 0.f; mac1[i] = 0.f; }
                #pragma unroll
                for (int ni = 0; ni < 16; ni++) {
                    int ncol = ni * 8 + q * 2;
                    int gcol = ubase + ncol;                  // global u column = l*4 + r
                    float bv0 = __ldg(b_u + gcol), bv1 = __ldg(b_u + gcol + 1);
                    float2 f0 = __half22float2(*(__half2*)&acc[ni][0]);
                    float2 f1 = __half22float2(*(__half2*)&acc[ni][1]);
                    float u0 = f0.x + bv0, u1 = f0.y + bv1;
                    float u2 = f1.x + bv0, u3 = f1.y + bv1;
                    su0 += u0 * u0 + u1 * u1;
                    su1 += u2 * u2 + u3 * u3;
                    int l = gcol >> 2;
                    float rv0 = __half2float(rs[r0 * RSTRIDE + l]);
                    float rv1 = __half2float(rs[r1 * RSTRIDE + l]);
                    float m0 = u0 * rv0, m1 = u1 * rv0;       // even q: ranks (0,1); odd q: (2,3)
                    float m2 = u2 * rv1, m3 = u3 * rv1;
                    float p0 = __shfl_xor_sync(~0u, m0, 1);
                    float p1 = __shfl_xor_sync(~0u, m1, 1);
                    float p2 = __shfl_xor_sync(~0u, m2, 1);
                    float p3 = __shfl_xor_sync(~0u, m3, 1);
                    float v0[4] = { m0, m1, p0, p1 };
                    float v1[4] = { m2, m3, p2, p3 };
                    #pragma unroll
                    for (int i2 = 0; i2 < 4; i2++)
                        #pragma unroll
                        for (int j2 = 0; j2 <= i2; j2++) {
                            mac0[i2 * (i2 + 1) / 2 + j2] += v0[i2] * v0[j2];
                            mac1[i2 * (i2 + 1) / 2 + j2] += v1[i2] * v1[j2];
                        }
                }
                su0 += __shfl_xor_sync(~0u, su0, 1); su0 += __shfl_xor_sync(~0u, su0, 2);
                su1 += __shfl_xor_sync(~0u, su1, 1); su1 += __shfl_xor_sync(~0u, su1, 2);
                #pragma unroll
                for (int i = 0; i < 10; i++) {    // combine even-latent (q0) + odd-latent (q2)
                    mac0[i] += __shfl_xor_sync(~0u, mac0[i], 2);
                    mac1[i] += __shfl_xor_sync(~0u, mac1[i], 2);
                }
                if (q == 0) {
                    stats[r0 * NSTATS + 3] += su0;
                    stats[r1 * NSTATS + 3] += su1;
                    #pragma unroll
                    for (int i = 0; i < 10; i++) {
                        stats[r0 * NSTATS + 4 + i] += mac0[i];
                        stats[r1 * NSTATS + 4 + i] += mac1[i];
                    }
                }
            }
        }

        // single barrier: makes stage s+1 visible everywhere AND frees slot of stage s
        if (s + 2 < NSTAGES) { CP_WAIT(1); } else { CP_WAIT(0); }
        __syncthreads();
    }

    // ---- per-row finish: logdet(I + MtM) via 4x4 Cholesky, then KL ----
    double klsum = 0.0;
    if (tid < MROWS) {
        const float* st = stats + tid * NSTATS;
        float mu_sq = st[0], sum_d = st[1], logz = st[2], su = st[3];
        float a00 = 1.f + st[4];
        float a10 = st[5],  a11 = 1.f + st[6];
        float a20 = st[7],  a21 = st[8],  a22 = 1.f + st[9];
        float a30 = st[10], a31 = st[11], a32 = st[12], a33 = 1.f + st[13];
        float L00 = sqrtf(a00); float i0 = 1.f / L00;
        float L10 = a10 * i0, L20 = a20 * i0, L30 = a30 * i0;
        float L11 = sqrtf(a11 - L10 * L10); float i1 = 1.f / L11;
        float L21 = (a21 - L20 * L10) * i1;
        float L31 = (a31 - L30 * L10) * i1;
        float L22 = sqrtf(a22 - L20 * L20 - L21 * L21); float i2 = 1.f / L22;
        float L32 = (a32 - L30 * L20 - L31 * L21) * i2;
        float L33 = sqrtf(a33 - L30 * L30 - L31 * L31 - L32 * L32);
        float logdetlr = 2.f * (logf(L00) + logf(L11) + logf(L22) + logf(L33));
        float kl = 0.5f * (sum_d + su + mu_sq - (float)LATENT - logz - logdetlr);
        klsum = (double)kl;
    }
    #pragma unroll
    for (int off = 16; off; off >>= 1) klsum += __shfl_down_sync(~0u, klsum, off);
    __shared__ double wsum[8];
    if (lane == 0) wsum[wid] = klsum;
    __syncthreads();
    if (tid == 0) {
        double ssum = 0.0;
        #pragma unroll
        for (int i = 0; i < 8; i++) ssum += wsum[i];
        atomicAdd(&g_sum, ssum);
    }
}

__global__ void finalize_kernel(float* out, int N) {
    out[0] = (float)(g_sum / (double)N);
}

extern "C" void kernel_launch(void* const* d_in, const int* in_sizes, int n_in,
                              void* d_out, int out_size) {
    const float* x    = (const float*)d_in[0];
    const float* W_mu = (const float*)d_in[1];
    const float* b_mu = (const float*)d_in[2];
    const float* W_u  = (const float*)d_in[3];
    const float* b_u  = (const float*)d_in[4];
    const float* W_d  = (const float*)d_in[5];
    const float* b_d  = (const float*)d_in[6];
    const int N = in_sizes[0] / HIDDEN;

    const size_t smem_bytes =
        (size_t)(MROWS * XSTRIDE + NRING * WS_ELEMS + 128 * RSTRIDE) * sizeof(__half) +
        (size_t)(128 * NSTATS) * sizeof(float);

    cudaFuncSetAttribute(lrg_main, cudaFuncAttributeMaxDynamicSharedMemorySize,
                         (int)smem_bytes);

    zero_kernel<<<1, 1>>>();
    convertW_kernel<<<(NTOT * HIDDEN + 255) / 256, 256>>>(W_mu, W_u, W_d);
    lrg_main<<<N / MROWS, THREADS, smem_bytes>>>(x, b_mu, b_u, b_d);
    finalize_kernel<<<1, 1>>>((float*)d_out, N);
}